// round 11
// baseline (speedup 1.0000x reference)
#include <cuda_runtime.h>
#include <cuda_fp16.h>

#define N_NODES 100000
#define D_FEAT  128
#define NEG_SLOPE 0.1f

// scratch (allocation-free rule: __device__ globals)
__device__ __half g_node_sum_h[N_NODES];   // fp16 node row-sums (fits smem)
__device__ float  g_r1[N_NODES];

// Kernel A: one warp per 4 nodes (measured-best config, R8: 11.5us).
// Lane l loads float4 #l of each of the 4 rows (MLP=4). N_NODES % 4 == 0,
// so every in-range warp has a full group. Writes fp16 sums + zeroes r1.
__global__ void node_sum_kernel(const float* __restrict__ feat) {
    int gtid = blockIdx.x * blockDim.x + threadIdx.x;
    int warp = gtid >> 5;
    int lane = gtid & 31;
    int node0 = warp * 4;
    if (node0 >= N_NODES) return;

    const float4* f4 = reinterpret_cast<const float4*>(feat);
    float4 v0 = f4[(size_t)(node0 + 0) * 32 + lane];
    float4 v1 = f4[(size_t)(node0 + 1) * 32 + lane];
    float4 v2 = f4[(size_t)(node0 + 2) * 32 + lane];
    float4 v3 = f4[(size_t)(node0 + 3) * 32 + lane];

    float s0 = (v0.x + v0.y) + (v0.z + v0.w);
    float s1 = (v1.x + v1.y) + (v1.z + v1.w);
    float s2 = (v2.x + v2.y) + (v2.z + v2.w);
    float s3 = (v3.x + v3.y) + (v3.z + v3.w);
    #pragma unroll
    for (int o = 16; o > 0; o >>= 1) {
        s0 += __shfl_xor_sync(0xFFFFFFFFu, s0, o);
        s1 += __shfl_xor_sync(0xFFFFFFFFu, s1, o);
        s2 += __shfl_xor_sync(0xFFFFFFFFu, s2, o);
        s3 += __shfl_xor_sync(0xFFFFFFFFu, s3, o);
    }
    if (lane == 0) {
        g_node_sum_h[node0 + 0] = __float2half_rn(s0);  g_r1[node0 + 0] = 0.0f;
        g_node_sum_h[node0 + 1] = __float2half_rn(s1);  g_r1[node0 + 1] = 0.0f;
        g_node_sum_h[node0 + 2] = __float2half_rn(s2);  g_r1[node0 + 2] = 0.0f;
        g_node_sum_h[node0 + 3] = __float2half_rn(s3);  g_r1[node0 + 3] = 0.0f;
    }
}

// Kernel B: persistent, 1 block/SM, full fp16 node_sum staged in SMEM.
// Random gathers hit smem banks (conflict ~3-4) instead of 32 L2 lines per
// warp; atomics remain fp32 REDG into L2-resident g_r1.
#define B_BLOCKS  148
#define B_THREADS 1024
#define SM_NS_BYTES (N_NODES * 2)          // 200000 B, = 12500 int4 exactly

__global__ void __launch_bounds__(B_THREADS, 1)
edge_scatter_kernel(const int* __restrict__ src,
                    const int* __restrict__ dst,
                    int n_edges4, int n_edges) {
    extern __shared__ __half sm_ns[];

    // Cooperative fill: 12500 int4 (L2-broadcast across SMs after first touch)
    {
        const int4* ns4 = reinterpret_cast<const int4*>(g_node_sum_h);
        int4* sm4 = reinterpret_cast<int4*>(sm_ns);
        for (int i = threadIdx.x; i < SM_NS_BYTES / 16; i += B_THREADS)
            sm4[i] = ns4[i];
    }
    __syncthreads();

    const int4* src4 = reinterpret_cast<const int4*>(src);
    const int4* dst4 = reinterpret_cast<const int4*>(dst);
    int stride = gridDim.x * B_THREADS;
    for (int i = blockIdx.x * B_THREADS + threadIdx.x; i < n_edges4; i += stride) {
        int4 s = src4[i];
        int4 d = dst4[i];
        float m0 = __half2float(sm_ns[s.x]);
        float m1 = __half2float(sm_ns[s.y]);
        float m2 = __half2float(sm_ns[s.z]);
        float m3 = __half2float(sm_ns[s.w]);
        atomicAdd(&g_r1[d.x], m0);
        atomicAdd(&g_r1[d.y], m1);
        atomicAdd(&g_r1[d.z], m2);
        atomicAdd(&g_r1[d.w], m3);
    }

    // Scalar tail (n_edges % 4), one thread, smem already filled in block 0.
    if (blockIdx.x == 0 && threadIdx.x == 0) {
        for (int e = n_edges4 * 4; e < n_edges; e++)
            atomicAdd(&g_r1[dst[e]], __half2float(sm_ns[src[e]]));
    }
}

// Kernel C: leaky-relu chain + truncate-toward-zero (astype(int32) semantics),
// written as float32 (harness __output__ dtype).
__global__ void epilogue_kernel(float* __restrict__ out) {
    int i = blockIdx.x * blockDim.x + threadIdx.x;
    if (i >= N_NODES) return;
    float r1 = g_r1[i];
    float a1 = (r1 >= 0.0f) ? r1 : NEG_SLOPE * r1;
    float r2 = 16.0f * a1;                       // HIDDEN = 16
    float a2 = (r2 >= 0.0f) ? r2 : NEG_SLOPE * r2;
    float r3 = 10.0f * a2;                       // N_CLASSES = 10
    out[i] = truncf(r3);
}

extern "C" void kernel_launch(void* const* d_in, const int* in_sizes, int n_in,
                              void* d_out, int out_size) {
    const float* feat = (const float*)d_in[0];
    const int*   esrc = (const int*)d_in[1];
    const int*   edst = (const int*)d_in[2];
    int n_edges = in_sizes[1];
    float* out = (float*)d_out;

    // Kernel A: warp per 4 nodes (R8 best config)
    {
        int threads = 256;                        // 8 warps = 32 nodes/block
        int nodes_per_block = (threads / 32) * 4;
        int blocks = (N_NODES + nodes_per_block - 1) / nodes_per_block;
        node_sum_kernel<<<blocks, threads>>>(feat);
    }
    // Kernel B: persistent, smem-staged fp16 node_sum
    {
        static int smem_set = 0;
        if (!smem_set) {
            cudaFuncSetAttribute(edge_scatter_kernel,
                                 cudaFuncAttributeMaxDynamicSharedMemorySize,
                                 SM_NS_BYTES);
            smem_set = 1;
        }
        int n4 = n_edges / 4;
        edge_scatter_kernel<<<B_BLOCKS, B_THREADS, SM_NS_BYTES>>>(
            esrc, edst, n4, n_edges);
    }
    // Kernel C
    {
        int threads = 256;
        int blocks = (N_NODES + threads - 1) / threads;
        epilogue_kernel<<<blocks, threads>>>(out);
    }
}

// round 12
// speedup vs baseline: 1.0508x; 1.0508x over previous
#include <cuda_runtime.h>

#define N_NODES 100000
#define D_FEAT  128
#define NEG_SLOPE 0.1f

// scratch (allocation-free rule: __device__ globals)
__device__ float g_node_sum[N_NODES];
__device__ float g_r1[N_NODES];

// Kernel A: one warp per 4 nodes (measured-best config: 11.4us).
// Lane l streams float4 #l of each of the 4 rows with __ldcs (evict-first,
// read-once data). N_NODES % 4 == 0 -> full groups. Zeroes r1 too.
__global__ void node_sum_kernel(const float* __restrict__ feat) {
    int gtid = blockIdx.x * blockDim.x + threadIdx.x;
    int warp = gtid >> 5;
    int lane = gtid & 31;
    int node0 = warp * 4;
    if (node0 >= N_NODES) return;

    const float4* f4 = reinterpret_cast<const float4*>(feat);
    float4 v0 = __ldcs(&f4[(size_t)(node0 + 0) * 32 + lane]);
    float4 v1 = __ldcs(&f4[(size_t)(node0 + 1) * 32 + lane]);
    float4 v2 = __ldcs(&f4[(size_t)(node0 + 2) * 32 + lane]);
    float4 v3 = __ldcs(&f4[(size_t)(node0 + 3) * 32 + lane]);

    float s0 = (v0.x + v0.y) + (v0.z + v0.w);
    float s1 = (v1.x + v1.y) + (v1.z + v1.w);
    float s2 = (v2.x + v2.y) + (v2.z + v2.w);
    float s3 = (v3.x + v3.y) + (v3.z + v3.w);
    #pragma unroll
    for (int o = 16; o > 0; o >>= 1) {
        s0 += __shfl_xor_sync(0xFFFFFFFFu, s0, o);
        s1 += __shfl_xor_sync(0xFFFFFFFFu, s1, o);
        s2 += __shfl_xor_sync(0xFFFFFFFFu, s2, o);
        s3 += __shfl_xor_sync(0xFFFFFFFFu, s3, o);
    }
    if (lane == 0) {
        g_node_sum[node0 + 0] = s0;  g_r1[node0 + 0] = 0.0f;
        g_node_sum[node0 + 1] = s1;  g_r1[node0 + 1] = 0.0f;
        g_node_sum[node0 + 2] = s2;  g_r1[node0 + 2] = 0.0f;
        g_node_sum[node0 + 3] = s3;  g_r1[node0 + 3] = 0.0f;
    }
}

// Kernel B: per-edge scatter-add of precomputed node sums (indices int32).
// 2 edges/thread via int2 loads (8B coalesced): shallower per-thread queue,
// more warps per SM to spread the REDG stream (4/thread=26us, 8/thread=28us,
// probing 2/thread). node_sum/r1 (400KB each) stay L2-resident.
__global__ void __launch_bounds__(256)
edge_scatter_kernel(const int* __restrict__ src,
                    const int* __restrict__ dst,
                    int n_edges2) {
    int i = blockIdx.x * blockDim.x + threadIdx.x;
    if (i >= n_edges2) return;
    const int2* src2 = reinterpret_cast<const int2*>(src);
    const int2* dst2 = reinterpret_cast<const int2*>(dst);
    int2 s = src2[i];
    int2 d = dst2[i];
    float m0 = g_node_sum[s.x];
    float m1 = g_node_sum[s.y];
    atomicAdd(&g_r1[d.x], m0);
    atomicAdd(&g_r1[d.y], m1);
}

// Tail kernel for n_edges not divisible by 2 (launched only if needed).
__global__ void edge_scatter_tail_kernel(const int* __restrict__ src,
                                         const int* __restrict__ dst,
                                         int start, int n_edges) {
    int i = start + blockIdx.x * blockDim.x + threadIdx.x;
    if (i < n_edges)
        atomicAdd(&g_r1[dst[i]], g_node_sum[src[i]]);
}

// Kernel C: leaky-relu chain + truncate-toward-zero (astype(int32) semantics),
// written as float32 (harness __output__ dtype).
__global__ void epilogue_kernel(float* __restrict__ out) {
    int i = blockIdx.x * blockDim.x + threadIdx.x;
    if (i >= N_NODES) return;
    float r1 = g_r1[i];
    float a1 = (r1 >= 0.0f) ? r1 : NEG_SLOPE * r1;
    float r2 = 16.0f * a1;                       // HIDDEN = 16
    float a2 = (r2 >= 0.0f) ? r2 : NEG_SLOPE * r2;
    float r3 = 10.0f * a2;                       // N_CLASSES = 10
    out[i] = truncf(r3);
}

extern "C" void kernel_launch(void* const* d_in, const int* in_sizes, int n_in,
                              void* d_out, int out_size) {
    const float* feat = (const float*)d_in[0];
    const int*   esrc = (const int*)d_in[1];
    const int*   edst = (const int*)d_in[2];
    int n_edges = in_sizes[1];
    float* out = (float*)d_out;

    // Kernel A: warp per 4 nodes
    {
        int threads = 256;                        // 8 warps = 32 nodes/block
        int nodes_per_block = (threads / 32) * 4;
        int blocks = (N_NODES + nodes_per_block - 1) / nodes_per_block;
        node_sum_kernel<<<blocks, threads>>>(feat);
    }
    // Kernel B: 2 edges per thread
    {
        int n2 = n_edges / 2;
        int threads = 256;
        int blocks = (n2 + threads - 1) / threads;
        if (blocks > 0)
            edge_scatter_kernel<<<blocks, threads>>>(esrc, edst, n2);
        int tail_start = n2 * 2;
        int tail = n_edges - tail_start;
        if (tail > 0)
            edge_scatter_tail_kernel<<<1, 32>>>(esrc, edst, tail_start, n_edges);
    }
    // Kernel C
    {
        int threads = 256;
        int blocks = (N_NODES + threads - 1) / threads;
        epilogue_kernel<<<blocks, threads>>>(out);
    }
}

// round 13
// speedup vs baseline: 1.1108x; 1.0571x over previous
#include <cuda_runtime.h>
#include <cuda_fp16.h>

#define N_NODES 100000
#define D_FEAT  128
#define NEG_SLOPE 0.1f

// scratch (allocation-free rule: __device__ globals)
// node_sum kept as fp16: 200KB -> fits entirely in one SM's 228KB L1, so
// kernel B's random gathers become L1 hits and stay off the LTS/atomic path.
__device__ __half g_node_sum_h[N_NODES];
__device__ float  g_r1[N_NODES];

// Kernel A: one warp per 4 nodes (measured-best shape, plain loads).
// Lane l loads float4 #l of each of the 4 rows (MLP=4). N_NODES % 4 == 0.
// Writes fp16 node sums + zeroes r1.
__global__ void node_sum_kernel(const float* __restrict__ feat) {
    int gtid = blockIdx.x * blockDim.x + threadIdx.x;
    int warp = gtid >> 5;
    int lane = gtid & 31;
    int node0 = warp * 4;
    if (node0 >= N_NODES) return;

    const float4* f4 = reinterpret_cast<const float4*>(feat);
    float4 v0 = f4[(size_t)(node0 + 0) * 32 + lane];
    float4 v1 = f4[(size_t)(node0 + 1) * 32 + lane];
    float4 v2 = f4[(size_t)(node0 + 2) * 32 + lane];
    float4 v3 = f4[(size_t)(node0 + 3) * 32 + lane];

    float s0 = (v0.x + v0.y) + (v0.z + v0.w);
    float s1 = (v1.x + v1.y) + (v1.z + v1.w);
    float s2 = (v2.x + v2.y) + (v2.z + v2.w);
    float s3 = (v3.x + v3.y) + (v3.z + v3.w);
    #pragma unroll
    for (int o = 16; o > 0; o >>= 1) {
        s0 += __shfl_xor_sync(0xFFFFFFFFu, s0, o);
        s1 += __shfl_xor_sync(0xFFFFFFFFu, s1, o);
        s2 += __shfl_xor_sync(0xFFFFFFFFu, s2, o);
        s3 += __shfl_xor_sync(0xFFFFFFFFu, s3, o);
    }
    if (lane == 0) {
        g_node_sum_h[node0 + 0] = __float2half_rn(s0);  g_r1[node0 + 0] = 0.0f;
        g_node_sum_h[node0 + 1] = __float2half_rn(s1);  g_r1[node0 + 1] = 0.0f;
        g_node_sum_h[node0 + 2] = __float2half_rn(s2);  g_r1[node0 + 2] = 0.0f;
        g_node_sum_h[node0 + 3] = __float2half_rn(s3);  g_r1[node0 + 3] = 0.0f;
    }
}

// Kernel B: 2 edges/thread (measured-best). Index streams use __ldcs
// (evict-first) so they don't evict the L1-resident fp16 node_sum working set;
// gathers use __ldg (L1-cached). Atomics (REDG) go straight to L2 and now own
// the LTS pipe alone.
__global__ void __launch_bounds__(256)
edge_scatter_kernel(const int* __restrict__ src,
                    const int* __restrict__ dst,
                    int n_edges2) {
    int i = blockIdx.x * blockDim.x + threadIdx.x;
    if (i >= n_edges2) return;
    const int2* src2 = reinterpret_cast<const int2*>(src);
    const int2* dst2 = reinterpret_cast<const int2*>(dst);
    int2 s = __ldcs(&src2[i]);
    int2 d = __ldcs(&dst2[i]);
    float m0 = __half2float(__ldg(&g_node_sum_h[s.x]));
    float m1 = __half2float(__ldg(&g_node_sum_h[s.y]));
    atomicAdd(&g_r1[d.x], m0);
    atomicAdd(&g_r1[d.y], m1);
}

// Tail kernel for n_edges not divisible by 2 (launched only if needed).
__global__ void edge_scatter_tail_kernel(const int* __restrict__ src,
                                         const int* __restrict__ dst,
                                         int start, int n_edges) {
    int i = start + blockIdx.x * blockDim.x + threadIdx.x;
    if (i < n_edges)
        atomicAdd(&g_r1[dst[i]], __half2float(g_node_sum_h[src[i]]));
}

// Kernel C: leaky-relu chain + truncate-toward-zero (astype(int32) semantics),
// written as float32 (harness __output__ dtype).
__global__ void epilogue_kernel(float* __restrict__ out) {
    int i = blockIdx.x * blockDim.x + threadIdx.x;
    if (i >= N_NODES) return;
    float r1 = g_r1[i];
    float a1 = (r1 >= 0.0f) ? r1 : NEG_SLOPE * r1;
    float r2 = 16.0f * a1;                       // HIDDEN = 16
    float a2 = (r2 >= 0.0f) ? r2 : NEG_SLOPE * r2;
    float r3 = 10.0f * a2;                       // N_CLASSES = 10
    out[i] = truncf(r3);
}

extern "C" void kernel_launch(void* const* d_in, const int* in_sizes, int n_in,
                              void* d_out, int out_size) {
    const float* feat = (const float*)d_in[0];
    const int*   esrc = (const int*)d_in[1];
    const int*   edst = (const int*)d_in[2];
    int n_edges = in_sizes[1];
    float* out = (float*)d_out;

    // Kernel A: warp per 4 nodes
    {
        int threads = 256;                        // 8 warps = 32 nodes/block
        int nodes_per_block = (threads / 32) * 4;
        int blocks = (N_NODES + nodes_per_block - 1) / nodes_per_block;
        node_sum_kernel<<<blocks, threads>>>(feat);
    }
    // Kernel B: 2 edges per thread
    {
        int n2 = n_edges / 2;
        int threads = 256;
        int blocks = (n2 + threads - 1) / threads;
        if (blocks > 0)
            edge_scatter_kernel<<<blocks, threads>>>(esrc, edst, n2);
        int tail_start = n2 * 2;
        int tail = n_edges - tail_start;
        if (tail > 0)
            edge_scatter_tail_kernel<<<1, 32>>>(esrc, edst, tail_start, n_edges);
    }
    // Kernel C
    {
        int threads = 256;
        int blocks = (N_NODES + threads - 1) / threads;
        epilogue_kernel<<<blocks, threads>>>(out);
    }
}